// round 5
// baseline (speedup 1.0000x reference)
#include <cuda_runtime.h>
#include <math.h>
#include <stdint.h>

#define NUM_LEVEL 16
#define N_POINTS  262144

struct LevelMeta {
    float    scale;
    uint32_t res;
    uint32_t offset;   // in float2 entries
    uint32_t mask;     // hsize-1 (hashed levels: hsize = 2^19)
    uint32_t hashed;
    uint32_t pad;
};

struct Meta {
    LevelMeta lv[NUM_LEVEL];
};

__global__ void __launch_bounds__(256, 6)
grid_encode_kernel(const float* __restrict__ pts,
                   const float2* __restrict__ emb,
                   float2* __restrict__ out,
                   Meta meta)
{
    const uint32_t tid = blockIdx.x * blockDim.x + threadIdx.x;
    // grid is exact: N_POINTS*16 / 256 blocks

    const uint32_t n = tid >> 4;     // point index
    const uint32_t l = tid & 15;     // level index

    // 16 consecutive threads share one point: L1 broadcast
    const float inx = __ldg(pts + n * 3 + 0);
    const float iny = __ldg(pts + n * 3 + 1);
    const float inz = __ldg(pts + n * 3 + 2);

    const LevelMeta m = meta.lv[l];

    const float px = (inx + 1.0f) * 0.5f * m.scale;
    const float py = (iny + 1.0f) * 0.5f * m.scale;
    const float pz = (inz + 1.0f) * 0.5f * m.scale;

    const float gx = floorf(px), gy = floorf(py), gz = floorf(pz);
    const float fx = px - gx,   fy = py - gy,   fz = pz - gz;

    const uint32_t ix = (uint32_t)gx;
    const uint32_t iy = (uint32_t)gy;
    const uint32_t iz = (uint32_t)gz;

    const float2* __restrict__ table = emb + m.offset;

    // Phase 1: all 8 indices. Keep the dense/hash branch divergent (fastest in
    // practice) but batch each side's loads before any consumer.
    uint32_t idx[8];
    if (m.hashed) {
        const uint32_t mask = m.mask;
        const uint32_t ty0 = iy * 2654435761u;
        const uint32_t ty1 = ty0 + 2654435761u;
        const uint32_t tz0 = iz * 805459861u;
        const uint32_t tz1 = tz0 + 805459861u;
        idx[0] = ( ix        ^ ty0 ^ tz0) & mask;
        idx[1] = ((ix + 1u)  ^ ty0 ^ tz0) & mask;
        idx[2] = ( ix        ^ ty1 ^ tz0) & mask;
        idx[3] = ((ix + 1u)  ^ ty1 ^ tz0) & mask;
        idx[4] = ( ix        ^ ty0 ^ tz1) & mask;
        idx[5] = ((ix + 1u)  ^ ty0 ^ tz1) & mask;
        idx[6] = ( ix        ^ ty1 ^ tz1) & mask;
        idx[7] = ((ix + 1u)  ^ ty1 ^ tz1) & mask;
    } else {
        const uint32_t r  = m.res;
        const uint32_t r2 = r * r;
        const uint32_t base = ix + iy * r + iz * r2;
        idx[0] = base;
        idx[1] = base + 1u;
        idx[2] = base + r;
        idx[3] = base + r + 1u;
        idx[4] = base + r2;
        idx[5] = base + r2 + 1u;
        idx[6] = base + r2 + r;
        idx[7] = base + r2 + r + 1u;
    }

    // Phase 2: 8 independent gathers in flight (MLP=8)
    float2 f0 = __ldg(table + idx[0]);
    float2 f1 = __ldg(table + idx[1]);
    float2 f2 = __ldg(table + idx[2]);
    float2 f3 = __ldg(table + idx[3]);
    float2 f4 = __ldg(table + idx[4]);
    float2 f5 = __ldg(table + idx[5]);
    float2 f6 = __ldg(table + idx[6]);
    float2 f7 = __ldg(table + idx[7]);

    // Phase 3: trilinear blend, weights recomputed inline (FMA pipe is idle)
    const float ox = 1.0f - fx, oy = 1.0f - fy, oz = 1.0f - fz;
    const float w00 = ox * oy, w10 = fx * oy, w01 = ox * fy, w11 = fx * fy;

    float accx, accy;
    {
        const float a = w00 * oz, b = w10 * oz, c = w01 * oz, d = w11 * oz;
        accx = a * f0.x; accy = a * f0.y;
        accx = fmaf(b, f1.x, accx); accy = fmaf(b, f1.y, accy);
        accx = fmaf(c, f2.x, accx); accy = fmaf(c, f2.y, accy);
        accx = fmaf(d, f3.x, accx); accy = fmaf(d, f3.y, accy);
    }
    {
        const float a = w00 * fz, b = w10 * fz, c = w01 * fz, d = w11 * fz;
        accx = fmaf(a, f4.x, accx); accy = fmaf(a, f4.y, accy);
        accx = fmaf(b, f5.x, accx); accy = fmaf(b, f5.y, accy);
        accx = fmaf(c, f6.x, accx); accy = fmaf(c, f6.y, accy);
        accx = fmaf(d, f7.x, accx); accy = fmaf(d, f7.y, accy);
    }

    out[n * (uint32_t)NUM_LEVEL + l] = make_float2(accx, accy);
}

// Host-side meta, bit-matching the reference's double-precision math.
static void compute_meta(Meta& M)
{
    const double ls = 1.38191288;
    const double lg = log2(ls);
    uint32_t off = 0;
    for (int i = 0; i < NUM_LEVEL; ++i) {
        double s   = exp2((double)i * lg) * 16.0 - 1.0;
        int    res = (int)ceil(s) + 1;

        double   res_meta = ceil(16.0 * pow(ls, (double)i));
        double   p3 = res_meta * res_meta * res_meta;
        uint32_t p  = (p3 > 524288.0) ? 524288u : (uint32_t)p3;
        p = ((p + 7u) / 8u) * 8u;

        unsigned long long res3 =
            (unsigned long long)res * (unsigned long long)res * (unsigned long long)res;
        bool hashed = res3 > (unsigned long long)p;

        M.lv[i].scale  = (float)s;
        M.lv[i].res    = (uint32_t)res;
        M.lv[i].offset = off;
        M.lv[i].mask   = p - 1u;
        M.lv[i].hashed = hashed ? 1u : 0u;
        M.lv[i].pad    = 0;

        off += p;
    }
}

extern "C" void kernel_launch(void* const* d_in, const int* in_sizes, int n_in,
                              void* d_out, int out_size)
{
    const float*  pts = (const float*)d_in[0];   // [N_POINTS, 3]
    const float2* emb = (const float2*)d_in[1];  // [offs[-1], 2]
    float2*       out = (float2*)d_out;          // [N_POINTS, 16] float2

    Meta M;
    compute_meta(M);

    const uint32_t total   = (uint32_t)N_POINTS * NUM_LEVEL;  // 4,194,304
    const uint32_t threads = 256;
    const uint32_t blocks  = total / threads;                 // exact

    grid_encode_kernel<<<blocks, threads>>>(pts, emb, out, M);
}

// round 6
// speedup vs baseline: 1.1379x; 1.1379x over previous
#include <cuda_runtime.h>
#include <math.h>
#include <stdint.h>

#define NUM_LEVEL 16
#define N_POINTS  262144

struct LevelMeta {
    float    scale;
    uint32_t res;
    uint32_t offset;   // in float2 entries
    uint32_t mask;     // hsize-1 (hashed levels: hsize = 2^19)
    uint32_t hashed;
    uint32_t pad;
};

struct Meta {
    LevelMeta lv[NUM_LEVEL];
};

__global__ void __launch_bounds__(256)
grid_encode_kernel(const float* __restrict__ pts,
                   const float2* __restrict__ emb,
                   float2* __restrict__ out,
                   Meta meta)
{
    const uint32_t tid = blockIdx.x * blockDim.x + threadIdx.x;
    // grid is exact: N_POINTS*16 / 256 blocks

    const uint32_t n = tid >> 4;     // point index
    const uint32_t l = tid & 15;     // level index

    // 16 consecutive threads share one point: L1 broadcast
    const float inx = __ldg(pts + n * 3 + 0);
    const float iny = __ldg(pts + n * 3 + 1);
    const float inz = __ldg(pts + n * 3 + 2);

    const LevelMeta m = meta.lv[l];

    const float px = (inx + 1.0f) * 0.5f * m.scale;
    const float py = (iny + 1.0f) * 0.5f * m.scale;
    const float pz = (inz + 1.0f) * 0.5f * m.scale;

    const float gx = floorf(px), gy = floorf(py), gz = floorf(pz);
    const float fx = px - gx,   fy = py - gy,   fz = pz - gz;

    const uint32_t ix = (uint32_t)gx;
    const uint32_t iy = (uint32_t)gy;
    const uint32_t iz = (uint32_t)gz;

    const float wx[2] = {1.0f - fx, fx};
    const float wy[2] = {1.0f - fy, fy};
    const float wz[2] = {1.0f - fz, fz};

    const float2* __restrict__ table = emb + m.offset;
    const uint32_t r      = m.res;
    const uint32_t r2     = r * r;
    const uint32_t mask   = m.mask;
    const bool     hashed = (m.hashed != 0u);

    float accx = 0.0f, accy = 0.0f;

    // Interleaved per-corner load+FMA (R1 shape), but index selection is
    // branchless: both dense and hash index computed, one SEL per corner.
    #pragma unroll
    for (int c = 0; c < 8; ++c) {
        const uint32_t bx = (uint32_t)(c & 1);
        const uint32_t by = (uint32_t)((c >> 1) & 1);
        const uint32_t bz = (uint32_t)(c >> 2);
        const uint32_t cx = ix + bx;
        const uint32_t cy = iy + by;
        const uint32_t cz = iz + bz;

        const uint32_t hidx = (cx ^ (cy * 2654435761u) ^ (cz * 805459861u)) & mask;
        const uint32_t didx = cx + cy * r + cz * r2;   // < hsize by construction
        const uint32_t idx  = hashed ? hidx : didx;    // SEL, no branch

        const float w = wx[bx] * wy[by] * wz[bz];
        const float2 f = __ldg(table + idx);
        accx = fmaf(w, f.x, accx);
        accy = fmaf(w, f.y, accy);
    }

    out[n * (uint32_t)NUM_LEVEL + l] = make_float2(accx, accy);
}

// Host-side meta, bit-matching the reference's double-precision math.
static void compute_meta(Meta& M)
{
    const double ls = 1.38191288;
    const double lg = log2(ls);
    uint32_t off = 0;
    for (int i = 0; i < NUM_LEVEL; ++i) {
        double s   = exp2((double)i * lg) * 16.0 - 1.0;
        int    res = (int)ceil(s) + 1;

        double   res_meta = ceil(16.0 * pow(ls, (double)i));
        double   p3 = res_meta * res_meta * res_meta;
        uint32_t p  = (p3 > 524288.0) ? 524288u : (uint32_t)p3;
        p = ((p + 7u) / 8u) * 8u;

        unsigned long long res3 =
            (unsigned long long)res * (unsigned long long)res * (unsigned long long)res;
        bool hashed = res3 > (unsigned long long)p;

        M.lv[i].scale  = (float)s;
        M.lv[i].res    = (uint32_t)res;
        M.lv[i].offset = off;
        M.lv[i].mask   = p - 1u;
        M.lv[i].hashed = hashed ? 1u : 0u;
        M.lv[i].pad    = 0;

        off += p;
    }
}

extern "C" void kernel_launch(void* const* d_in, const int* in_sizes, int n_in,
                              void* d_out, int out_size)
{
    const float*  pts = (const float*)d_in[0];   // [N_POINTS, 3]
    const float2* emb = (const float2*)d_in[1];  // [offs[-1], 2]
    float2*       out = (float2*)d_out;          // [N_POINTS, 16] float2

    Meta M;
    compute_meta(M);

    const uint32_t total   = (uint32_t)N_POINTS * NUM_LEVEL;  // 4,194,304
    const uint32_t threads = 256;
    const uint32_t blocks  = total / threads;                 // exact

    grid_encode_kernel<<<blocks, threads>>>(pts, emb, out, M);
}